// round 12
// baseline (speedup 1.0000x reference)
#include <cuda_runtime.h>
#include <cuda_bf16.h>

// AMSoftmaxLoss: score (2048 x 50257) fp32, labels (2048) int32 in {0,1}
// Exact two-wave flat partition: 2368 (= 2 x 148SM x 8) equal chunks of the
// flat element array; 4-deep LDG.128 inner loop; per-block <=2-row partials;
// last-arriving block scatters partials + epilogue.

#define NROWS 2048
#define CCOLS 50257
#define NBLK  2368             // exactly 2 waves at occupancy 8
#define BLK   256

#define TOTELEM (NROWS * CCOLS)            // 102,926,336
#define CHUNK   (TOTELEM / NBLK)           // 43465
#define REM     (TOTELEM - CHUNK * NBLK)   // 1216

__device__ float g_part[NBLK * 2];
__device__ unsigned int g_count = 0;       // self-resetting via atomicInc wrap

__device__ __forceinline__ float ex2f(float x) {
    float y;
    asm("ex2.approx.ftz.f32 %0, %1;" : "=f"(y) : "f"(x));
    return y;
}

#define SL2E (30.0f * 1.44269504088896340736f)   // S * log2(e)

// Sum of exp(S*x) over score[lo, hi), strided across the block, 4-deep MLP.
__device__ __forceinline__ float seg_sum(const float* __restrict__ score,
                                         int lo, int hi, int tid)
{
    const float* __restrict__ p = score + lo;
    const int len = hi - lo;

    float s0 = 0.f, s1 = 0.f, s2 = 0.f, s3 = 0.f;

    int peel = (-lo) & 3;                  // to 16B alignment
    if (peel > len) peel = len;
    if (tid < peel) s0 += ex2f(SL2E * p[tid]);

    const int n4 = (len - peel) >> 2;
    const float4* __restrict__ q = (const float4*)(p + peel);

    int i = tid;
    for (; i + 3 * BLK < n4; i += 4 * BLK) {   // 4 LDG.128 in flight
        float4 a = q[i];
        float4 b = q[i + BLK];
        float4 c = q[i + 2 * BLK];
        float4 d = q[i + 3 * BLK];
        s0 += ex2f(SL2E * a.x); s1 += ex2f(SL2E * a.y);
        s2 += ex2f(SL2E * a.z); s3 += ex2f(SL2E * a.w);
        s0 += ex2f(SL2E * b.x); s1 += ex2f(SL2E * b.y);
        s2 += ex2f(SL2E * b.z); s3 += ex2f(SL2E * b.w);
        s0 += ex2f(SL2E * c.x); s1 += ex2f(SL2E * c.y);
        s2 += ex2f(SL2E * c.z); s3 += ex2f(SL2E * c.w);
        s0 += ex2f(SL2E * d.x); s1 += ex2f(SL2E * d.y);
        s2 += ex2f(SL2E * d.z); s3 += ex2f(SL2E * d.w);
    }
    for (; i < n4; i += BLK) {
        float4 a = q[i];
        s0 += ex2f(SL2E * a.x); s1 += ex2f(SL2E * a.y);
        s2 += ex2f(SL2E * a.z); s3 += ex2f(SL2E * a.w);
    }
    const int done = peel + 4 * n4;
    if (tid < len - done) s0 += ex2f(SL2E * p[done + tid]);

    return (s0 + s1) + (s2 + s3);
}

__global__ __launch_bounds__(BLK) void amsm_kernel(
    const float* __restrict__ score,
    const int* __restrict__ labels,
    float* __restrict__ out)
{
    const int b   = blockIdx.x;
    const int tid = threadIdx.x;
    const int lane = tid & 31;
    const int wid  = tid >> 5;

    const int begin = b * CHUNK + (b < REM ? b : REM);
    const int end   = begin + CHUNK + (b < REM ? 1 : 0);
    const int r0    = begin / CCOLS;

    // A chunk of <= CHUNK+1 < CCOLS elements spans at most 2 rows.
    const int rowend0 = (r0 + 1) * CCOLS;
    const int mid = rowend0 < end ? rowend0 : end;

    float part0 = seg_sum(score, begin, mid, tid);
    float part1 = (mid < end) ? seg_sum(score, mid, end, tid) : 0.f;

    // Block-reduce both partials: warp shuffle, then cross-warp via smem.
    __shared__ float wsum[2][BLK / 32];
    #pragma unroll
    for (int off = 16; off > 0; off >>= 1) {
        part0 += __shfl_down_sync(0xFFFFFFFFu, part0, off);
        part1 += __shfl_down_sync(0xFFFFFFFFu, part1, off);
    }
    if (lane == 0) { wsum[0][wid] = part0; wsum[1][wid] = part1; }
    __syncthreads();

    __shared__ unsigned s_last;
    if (tid == 0) {
        float w0 = 0.f, w1 = 0.f;
        #pragma unroll
        for (int k = 0; k < BLK / 32; k++) { w0 += wsum[0][k]; w1 += wsum[1][k]; }
        g_part[b * 2 + 0] = w0;
        g_part[b * 2 + 1] = w1;
        __threadfence();
        unsigned old = atomicInc(&g_count, NBLK - 1);   // wraps -> self-reset
        s_last = (old == NBLK - 1) ? 1u : 0u;
    }
    __syncthreads();
    if (!s_last) return;

    // ---- Last-arriving block: scatter partials, per-row epilogue, mean ----
    __shared__ float rowsum[NROWS];
    for (int r = tid; r < NROWS; r += BLK) rowsum[r] = 0.f;
    __syncthreads();

    volatile float* gp = g_part;
    for (int blk = tid; blk < NBLK; blk += BLK) {
        int bb = blk * CHUNK + (blk < REM ? blk : REM);
        int fr = bb / CCOLS;
        float p0 = gp[blk * 2 + 0];
        float p1 = gp[blk * 2 + 1];
        atomicAdd(&rowsum[fr], p0);
        if (fr + 1 < NROWS) atomicAdd(&rowsum[fr + 1], p1);
    }
    __syncthreads();

    double acc = 0.0;
    for (int r = tid; r < NROWS; r += BLK) {
        int lab = labels[r] & 1;
        float m = lab ? 0.4f : 0.1f;
        float tg = __ldg(score + (size_t)r * CCOLS + lab);
        float num = 30.0f * (tg - m);
        float excl = rowsum[r] - ex2f(SL2E * tg);
        float denom = ex2f(num * 1.44269504088896340736f) + excl;
        acc += (double)(num - logf(denom));
    }

    __shared__ double dred[BLK];
    dred[tid] = acc;
    __syncthreads();
    #pragma unroll
    for (int off = BLK / 2; off > 0; off >>= 1) {
        if (tid < off) dred[tid] += dred[tid + off];
        __syncthreads();
    }
    if (tid == 0)
        out[0] = (float)(-dred[0] / (double)NROWS);
}

extern "C" void kernel_launch(void* const* d_in, const int* in_sizes, int n_in,
                              void* d_out, int out_size)
{
    const float* score = (const float*)d_in[0];
    const int* labels = (const int*)d_in[1];
    float* out = (float*)d_out;

    amsm_kernel<<<NBLK, BLK>>>(score, labels, out);
}